// round 4
// baseline (speedup 1.0000x reference)
#include <cuda_runtime.h>

// PartialDataLoss: directional Chamfer (template -> scan), sum of squared NN
// distances below 0.1.
//
// min_n d2[m,n] = |t_m|^2 + min_n (|s_n|^2 - 2 t_m.s_n)
//
// Kernel 1 (chamfer): each CTA owns one scan chunk (bx) and 1024 template
//   points (by). It packs its chunk into smem as f32x2 lanes:
//     tileA[p] = (-2x_{2p}, -2x_{2p+1}, -2y_{2p}, -2y_{2p+1})
//     tileB[p] = (-2z_{2p}, -2z_{2p+1}, |s_{2p}|^2, |s_{2p+1}|^2)
//   Inner loop: 3 fma.rn.f32x2 + 2 min.f32 per (2 scan pts x 1 template pt).
//   Per-chunk min written non-atomically to g_partial[m*CHUNKS + chunk].
// Kernel 2 (reduce): min over chunks, add |t_m|^2, threshold, sum.

#define BLOCK      256
#define TPT        4          // template points per thread
#define CHUNKS     63         // 63 * 7 = 441 CTAs ~= 148 * 3 (no straggler SMs)
#define PAIRS_MAX  400        // ceil(ceil(50000/63)/2) = 397
#define M_MAX      8192

__device__ float g_partial[M_MAX * CHUNKS];

__device__ __forceinline__ unsigned long long bcast2(float f) {
    unsigned long long r;
    asm("mov.b64 %0, {%1, %1};" : "=l"(r) : "f"(f));
    return r;
}

__global__ void __launch_bounds__(BLOCK)
chamfer_kernel(const float* __restrict__ scan, const float* __restrict__ tmpl,
               int N, int M) {
    __shared__ float4 tileA[PAIRS_MAX];
    __shared__ float4 tileB[PAIRS_MAX];

    const int chunkSize = (N + CHUNKS - 1) / CHUNKS;
    const int s0 = blockIdx.x * chunkSize;
    const int cnt = min(chunkSize, N - s0);
    const int pairs = (cnt + 1) >> 1;

    // Pack this CTA's scan chunk into smem (f32x2 lane layout).
    for (int p = threadIdx.x; p < pairs; p += BLOCK) {
        const int i0 = s0 + 2 * p;
        const bool has1 = (2 * p + 1) < cnt;
        float x0 = scan[3 * i0 + 0], y0 = scan[3 * i0 + 1], z0 = scan[3 * i0 + 2];
        float w0 = fmaf(x0, x0, fmaf(y0, y0, z0 * z0));
        float x1 = 0.f, y1 = 0.f, z1 = 0.f, w1 = __int_as_float(0x7f800000);
        if (has1) {
            x1 = scan[3 * i0 + 3]; y1 = scan[3 * i0 + 4]; z1 = scan[3 * i0 + 5];
            w1 = fmaf(x1, x1, fmaf(y1, y1, z1 * z1));
        }
        tileA[p] = make_float4(-2.f * x0, -2.f * x1, -2.f * y0, -2.f * y1);
        tileB[p] = make_float4(-2.f * z0, -2.f * z1, w0, w1);
    }

    // Template points for this CTA (broadcast each coord into both f32x2 lanes).
    const int base = blockIdx.y * (BLOCK * TPT) + threadIdx.x;
    unsigned long long txx[TPT], tyy[TPT], tzz[TPT];
    float mnl[TPT], mnh[TPT];
#pragma unroll
    for (int t = 0; t < TPT; t++) {
        int m = base + t * BLOCK;
        int mc = m < M ? m : (M - 1);          // clamped dups never written out
        txx[t] = bcast2(__ldg(&tmpl[3 * mc + 0]));
        tyy[t] = bcast2(__ldg(&tmpl[3 * mc + 1]));
        tzz[t] = bcast2(__ldg(&tmpl[3 * mc + 2]));
        mnl[t] = __int_as_float(0x7f800000);
        mnh[t] = __int_as_float(0x7f800000);
    }

    __syncthreads();

    const ulonglong2* tA = reinterpret_cast<const ulonglong2*>(tileA);
    const ulonglong2* tB = reinterpret_cast<const ulonglong2*>(tileB);

#pragma unroll 2
    for (int j = 0; j < pairs; j++) {
        const ulonglong2 A = tA[j];   // A.x = xx pair, A.y = yy pair
        const ulonglong2 B = tB[j];   // B.x = zz pair, B.y = ww pair
#pragma unroll
        for (int t = 0; t < TPT; t++) {
            asm("{\n\t"
                ".reg .b64 acc;\n\t"
                ".reg .f32 lo, hi;\n\t"
                "fma.rn.f32x2 acc, %2, %5, %8;\n\t"
                "fma.rn.f32x2 acc, %3, %6, acc;\n\t"
                "fma.rn.f32x2 acc, %4, %7, acc;\n\t"
                "mov.b64 {lo, hi}, acc;\n\t"
                "min.f32 %0, %0, lo;\n\t"
                "min.f32 %1, %1, hi;\n\t"
                "}"
                : "+f"(mnl[t]), "+f"(mnh[t])
                : "l"(txx[t]), "l"(tyy[t]), "l"(tzz[t]),
                  "l"(A.x), "l"(A.y), "l"(B.x), "l"(B.y));
        }
    }

#pragma unroll
    for (int t = 0; t < TPT; t++) {
        int m = base + t * BLOCK;
        if (m < M)
            g_partial[m * CHUNKS + blockIdx.x] = fminf(mnl[t], mnh[t]);
    }
}

__global__ void reduce_kernel(const float* __restrict__ tmpl, int M,
                              float* __restrict__ out) {
    __shared__ float warpsum[32];
    float local = 0.0f;
    for (int m = threadIdx.x; m < M; m += blockDim.x) {
        float mn = __int_as_float(0x7f800000);
        const float* row = &g_partial[m * CHUNKS];
#pragma unroll
        for (int c = 0; c < CHUNKS; c++)
            mn = fminf(mn, row[c]);
        float x = tmpl[3 * m + 0];
        float y = tmpl[3 * m + 1];
        float z = tmpl[3 * m + 2];
        float d2 = mn + fmaf(x, x, fmaf(y, y, z * z));
        if (d2 < 0.1f) local += d2;
    }
#pragma unroll
    for (int o = 16; o > 0; o >>= 1)
        local += __shfl_down_sync(0xFFFFFFFFu, local, o);
    if ((threadIdx.x & 31) == 0) warpsum[threadIdx.x >> 5] = local;
    __syncthreads();
    if (threadIdx.x < 32) {
        int nw = (blockDim.x + 31) >> 5;
        float v = (threadIdx.x < nw) ? warpsum[threadIdx.x] : 0.0f;
#pragma unroll
        for (int o = 16; o > 0; o >>= 1)
            v += __shfl_down_sync(0xFFFFFFFFu, v, o);
        if (threadIdx.x == 0) out[0] = v;
    }
}

extern "C" void kernel_launch(void* const* d_in, const int* in_sizes, int n_in,
                              void* d_out, int out_size) {
    const float* scan = (const float*)d_in[0];
    const float* tmpl = (const float*)d_in[1];
    const int N = in_sizes[0] / 3;
    const int M = in_sizes[1] / 3;

    dim3 grid(CHUNKS, (M + BLOCK * TPT - 1) / (BLOCK * TPT));
    chamfer_kernel<<<grid, BLOCK>>>(scan, tmpl, N, M);

    reduce_kernel<<<1, 1024>>>(tmpl, M, (float*)d_out);
}

// round 5
// speedup vs baseline: 2.0417x; 2.0417x over previous
#include <cuda_runtime.h>

// PartialDataLoss: directional Chamfer (template -> scan), thresholded sum.
//
// min_n d2[m,n] = |t_m|^2 + min_n (|s_n|^2 - 2 t_m.s_n)
//
// chamfer: CTA = (scan chunk bx, 1024 template pts by). Scan chunk packed in
//   smem as f32x2 lanes; inner loop = 3 fma.rn.f32x2 + 2 FMNMX per
//   (2 scan pts x 1 template pt), accumulator halves min'd in C++ so ptxas
//   allocates lo/hi onto the acc register pair (no MOVs).
//   Partial mins stored chunk-major: g_partial[chunk * MPAD + m] (coalesced).
// reduce1: 27 CTAs, thread m: min over 63 chunks (coalesced), add |t_m|^2,
//   threshold, block-sum -> g_blocksum[b].
// reduce2: single warp, deterministic sum of 27 partials.

#define BLOCK      256
#define TPT        4
#define CHUNKS     63         // 63 * 7 = 441 CTAs ~= 148 * 3
#define PAIRS_MAX  400        // ceil(ceil(50000/63)/2) = 397
#define MPAD       8192
#define RBLOCKS    27         // 27 * 256 = 6912 >= 6890

__device__ float g_partial[CHUNKS * MPAD];
__device__ float g_blocksum[RBLOCKS];

__device__ __forceinline__ unsigned long long bcast2(float f) {
    unsigned long long r;
    asm("mov.b64 %0, {%1, %1};" : "=l"(r) : "f"(f));
    return r;
}

__global__ void __launch_bounds__(BLOCK)
chamfer_kernel(const float* __restrict__ scan, const float* __restrict__ tmpl,
               int N, int M) {
    __shared__ float4 tileA[PAIRS_MAX];
    __shared__ float4 tileB[PAIRS_MAX];

    const int chunkSize = (N + CHUNKS - 1) / CHUNKS;
    const int s0 = blockIdx.x * chunkSize;
    const int cnt = min(chunkSize, N - s0);
    const int pairs = (cnt + 1) >> 1;

    // Pack this CTA's scan chunk into smem (f32x2 lane layout).
    for (int p = threadIdx.x; p < pairs; p += BLOCK) {
        const int i0 = s0 + 2 * p;
        const bool has1 = (2 * p + 1) < cnt;
        float x0 = scan[3 * i0 + 0], y0 = scan[3 * i0 + 1], z0 = scan[3 * i0 + 2];
        float w0 = fmaf(x0, x0, fmaf(y0, y0, z0 * z0));
        float x1 = 0.f, y1 = 0.f, z1 = 0.f, w1 = __int_as_float(0x7f800000);
        if (has1) {
            x1 = scan[3 * i0 + 3]; y1 = scan[3 * i0 + 4]; z1 = scan[3 * i0 + 5];
            w1 = fmaf(x1, x1, fmaf(y1, y1, z1 * z1));
        }
        tileA[p] = make_float4(-2.f * x0, -2.f * x1, -2.f * y0, -2.f * y1);
        tileB[p] = make_float4(-2.f * z0, -2.f * z1, w0, w1);
    }

    const int base = blockIdx.y * (BLOCK * TPT) + threadIdx.x;
    unsigned long long txx[TPT], tyy[TPT], tzz[TPT];
    float mnl[TPT], mnh[TPT];
#pragma unroll
    for (int t = 0; t < TPT; t++) {
        int m = base + t * BLOCK;
        int mc = m < M ? m : (M - 1);          // clamped dups never written out
        txx[t] = bcast2(__ldg(&tmpl[3 * mc + 0]));
        tyy[t] = bcast2(__ldg(&tmpl[3 * mc + 1]));
        tzz[t] = bcast2(__ldg(&tmpl[3 * mc + 2]));
        mnl[t] = __int_as_float(0x7f800000);
        mnh[t] = __int_as_float(0x7f800000);
    }

    __syncthreads();

    const ulonglong2* tA = reinterpret_cast<const ulonglong2*>(tileA);
    const ulonglong2* tB = reinterpret_cast<const ulonglong2*>(tileB);

#pragma unroll 2
    for (int j = 0; j < pairs; j++) {
        const ulonglong2 A = tA[j];   // A.x = xx pair, A.y = yy pair
        const ulonglong2 B = tB[j];   // B.x = zz pair, B.y = ww pair
#pragma unroll
        for (int t = 0; t < TPT; t++) {
            unsigned long long acc;
            // acc = txx*xx + ww ; acc += tyy*yy ; acc += tzz*zz   (2 lanes)
            asm("fma.rn.f32x2 %0, %1, %2, %3;"
                : "=l"(acc) : "l"(txx[t]), "l"(A.x), "l"(B.y));
            asm("fma.rn.f32x2 %0, %1, %2, %0;"
                : "+l"(acc) : "l"(tyy[t]), "l"(A.y));
            asm("fma.rn.f32x2 %0, %1, %2, %0;"
                : "+l"(acc) : "l"(tzz[t]), "l"(B.x));
            float2 d = *reinterpret_cast<float2*>(&acc);  // lo/hi = acc reg pair
            mnl[t] = fminf(mnl[t], d.x);
            mnh[t] = fminf(mnh[t], d.y);
        }
    }

#pragma unroll
    for (int t = 0; t < TPT; t++) {
        int m = base + t * BLOCK;
        if (m < M)
            g_partial[blockIdx.x * MPAD + m] = fminf(mnl[t], mnh[t]);  // coalesced
    }
}

__global__ void __launch_bounds__(BLOCK)
reduce1_kernel(const float* __restrict__ tmpl, int M) {
    __shared__ float warpsum[BLOCK / 32];
    const int m = blockIdx.x * BLOCK + threadIdx.x;

    float local = 0.0f;
    if (m < M) {
        float mn = __int_as_float(0x7f800000);
#pragma unroll
        for (int c = 0; c < CHUNKS; c++)
            mn = fminf(mn, g_partial[c * MPAD + m]);   // coalesced across threads
        float x = tmpl[3 * m + 0];
        float y = tmpl[3 * m + 1];
        float z = tmpl[3 * m + 2];
        float d2 = mn + fmaf(x, x, fmaf(y, y, z * z));
        if (d2 < 0.1f) local = d2;
    }

#pragma unroll
    for (int o = 16; o > 0; o >>= 1)
        local += __shfl_down_sync(0xFFFFFFFFu, local, o);
    if ((threadIdx.x & 31) == 0) warpsum[threadIdx.x >> 5] = local;
    __syncthreads();
    if (threadIdx.x < 32) {
        float v = (threadIdx.x < BLOCK / 32) ? warpsum[threadIdx.x] : 0.0f;
#pragma unroll
        for (int o = 4; o > 0; o >>= 1)
            v += __shfl_down_sync(0xFFFFFFFFu, v, o);
        if (threadIdx.x == 0) g_blocksum[blockIdx.x] = v;
    }
}

__global__ void reduce2_kernel(float* __restrict__ out) {
    if (threadIdx.x == 0) {
        float s = 0.0f;
#pragma unroll
        for (int b = 0; b < RBLOCKS; b++) s += g_blocksum[b];
        out[0] = s;
    }
}

extern "C" void kernel_launch(void* const* d_in, const int* in_sizes, int n_in,
                              void* d_out, int out_size) {
    const float* scan = (const float*)d_in[0];
    const float* tmpl = (const float*)d_in[1];
    const int N = in_sizes[0] / 3;
    const int M = in_sizes[1] / 3;

    dim3 grid(CHUNKS, (M + BLOCK * TPT - 1) / (BLOCK * TPT));
    chamfer_kernel<<<grid, BLOCK>>>(scan, tmpl, N, M);

    reduce1_kernel<<<RBLOCKS, BLOCK>>>(tmpl, M);
    reduce2_kernel<<<1, 32>>>((float*)d_out);
}